// round 1
// baseline (speedup 1.0000x reference)
#include <cuda_runtime.h>
#include <cuda_bf16.h>
#include <math.h>

// Problem constants (fixed shapes per reference)
#define T_DIM 4096
#define D_DIM 1024
#define NBLK  64      // T_DIM / 64
#define BK    32
#define SSTR  40      // shared stride (bf16 elems): 64+8 pad -> conflict-free .b32 frag loads

// ---------------- scratch (static device allocations; no cudaMalloc) -------
__device__ __nv_bfloat16 g_Mb [T_DIM * D_DIM];
__device__ __nv_bfloat16 g_MH [T_DIM * D_DIM];
__device__ __nv_bfloat16 g_MH2[T_DIM * D_DIM];
__device__ int                g_am[T_DIM];
__device__ unsigned long long g_rowmin[T_DIM];
__device__ double             g_mse;
__device__ double             g_rowloss;

// ---------------- helpers ---------------------------------------------------
__device__ __forceinline__ unsigned long long pack_key(float s, int idx) {
    unsigned int u = __float_as_uint(s);
    u = (u & 0x80000000u) ? ~u : (u | 0x80000000u);   // order-preserving float->uint
    return ((unsigned long long)u << 32) | (unsigned int)idx;
}
__device__ __forceinline__ unsigned long long ullmin2(unsigned long long a, unsigned long long b) {
    return a < b ? a : b;
}
__device__ __forceinline__ void mma16816(float* c, const unsigned* a, const unsigned* b) {
    asm volatile(
        "mma.sync.aligned.m16n8k16.row.col.f32.bf16.bf16.f32 "
        "{%0,%1,%2,%3}, {%4,%5,%6,%7}, {%8,%9}, {%0,%1,%2,%3};"
        : "+f"(c[0]), "+f"(c[1]), "+f"(c[2]), "+f"(c[3])
        : "r"(a[0]), "r"(a[1]), "r"(a[2]), "r"(a[3]), "r"(b[0]), "r"(b[1]));
}

// ---------------- kernel 0: reset accumulators / row-min keys ---------------
__global__ void init_kernel() {
    int t = blockIdx.x * blockDim.x + threadIdx.x;
    if (t < T_DIM) g_rowmin[t] = pack_key(9999.0f, 0);   // sentinel, index 0 (matches jnp.argmin on all-9999 row)
    if (t == 0) { g_mse = 0.0; g_rowloss = 0.0; }
}

// ---------------- kernel 1: build bf16 operands, am[], masked MSE -----------
__global__ void prep_kernel(const float* __restrict__ X, const float* __restrict__ H,
                            const float* __restrict__ C, const float* __restrict__ M) {
    int i = blockIdx.x;
    int t = threadIdx.x;                       // 256 threads
    const size_t base = (size_t)i * D_DIM;

    float bestv = 3.4e38f; int besti = 0;
    float msum = 0.f;
    for (int d = t; d < D_DIM; d += 256) {
        float m = M[base + d];
        float h = H[base + d];
        float mb = (m > 0.f) ? 1.f : 0.f;
        g_Mb [base + d] = __float2bfloat16(mb);
        g_MH [base + d] = __float2bfloat16(mb * h);
        g_MH2[base + d] = __float2bfloat16(mb * h * h);
        float e = (X[base + d] - (h - C[base + d])) * m;
        msum += e * e;
        if (m < bestv) { bestv = m; besti = d; }   // indices increase per-thread -> first occurrence
    }

    __shared__ float sv[256]; __shared__ int si[256]; __shared__ float ss[256];
    sv[t] = bestv; si[t] = besti; ss[t] = msum;
    __syncthreads();
    for (int o = 128; o > 0; o >>= 1) {
        if (t < o) {
            if (sv[t + o] < sv[t] || (sv[t + o] == sv[t] && si[t + o] < si[t])) {
                sv[t] = sv[t + o]; si[t] = si[t + o];
            }
            ss[t] += ss[t + o];
        }
        __syncthreads();
    }
    if (t == 0) {
        g_am[i] = si[0];
        atomicAdd(&g_mse, (double)ss[0]);
    }
}

// ---------------- kernel 2: fused symmetric 6-product GEMM + score argmin ---
__global__ __launch_bounds__(256, 1)
void gemm_kernel() {
    int bi = blockIdx.y, bj = blockIdx.x;
    if (bj < bi) return;                       // symmetry: upper triangle only

    __shared__ __align__(16) __nv_bfloat16 sA[3][64][SSTR];
    __shared__ __align__(16) __nv_bfloat16 sB[3][64][SSTR];
    __shared__ unsigned long long keyI[64], keyJ[64];

    const int tid  = threadIdx.x;
    const int lane = tid & 31;
    const int warp = tid >> 5;
    const int wm = warp >> 2;                  // 0..1 -> 32-row slab
    const int wn = warp & 3;                   // 0..3 -> 16-col slab
    const int g  = lane >> 2;                  // group id (row within frag)
    const int tg = lane & 3;                   // thread-in-group (col pair)

    if (tid < 64)            keyI[tid]      = ~0ull;
    else if (tid < 128)      keyJ[tid - 64] = ~0ull;

    float acc[6][2][2][4];
    #pragma unroll
    for (int a = 0; a < 6; a++)
        #pragma unroll
        for (int b = 0; b < 2; b++)
            #pragma unroll
            for (int c = 0; c < 2; c++)
                #pragma unroll
                for (int d = 0; d < 4; d++) acc[a][b][c][d] = 0.f;

    const int ib = bi * 64, jb = bj * 64;
    const int lrow = tid >> 2;                 // 0..63 (global-load row)
    const int lcg  = tid & 3;                  // 8-elem col group

    const __nv_bfloat16* gm0 = g_Mb;
    const __nv_bfloat16* gm1 = g_MH;
    const __nv_bfloat16* gm2 = g_MH2;
    const __nv_bfloat16* gms[3] = {gm0, gm1, gm2};

    for (int kt = 0; kt < D_DIM; kt += BK) {
        __syncthreads();
        #pragma unroll
        for (int m = 0; m < 3; m++) {
            float4 va = *(const float4*)(gms[m] + (size_t)(ib + lrow) * D_DIM + kt + lcg * 8);
            float4 vb = *(const float4*)(gms[m] + (size_t)(jb + lrow) * D_DIM + kt + lcg * 8);
            *(float4*)&sA[m][lrow][lcg * 8] = va;
            *(float4*)&sB[m][lrow][lcg * 8] = vb;
        }
        __syncthreads();

        #pragma unroll
        for (int kk = 0; kk < BK; kk += 16) {
            unsigned af[3][2][4];
            unsigned bfr[3][2][2];
            #pragma unroll
            for (int m = 0; m < 3; m++) {
                #pragma unroll
                for (int mf = 0; mf < 2; mf++) {
                    int r = wm * 32 + mf * 16 + g;
                    af[m][mf][0] = *(const unsigned*)&sA[m][r    ][kk + tg * 2    ];
                    af[m][mf][1] = *(const unsigned*)&sA[m][r + 8][kk + tg * 2    ];
                    af[m][mf][2] = *(const unsigned*)&sA[m][r    ][kk + tg * 2 + 8];
                    af[m][mf][3] = *(const unsigned*)&sA[m][r + 8][kk + tg * 2 + 8];
                }
                #pragma unroll
                for (int nf = 0; nf < 2; nf++) {
                    int cc = wn * 16 + nf * 8 + g;
                    bfr[m][nf][0] = *(const unsigned*)&sB[m][cc][kk + tg * 2    ];
                    bfr[m][nf][1] = *(const unsigned*)&sB[m][cc][kk + tg * 2 + 8];
                }
            }
            // 0:n(Mb,Mb) 1:G2a(MH,Mb) 2:G3a(MH2,Mb) 3:G2b(Mb,MH) 4:G3b(Mb,MH2) 5:G4(MH,MH)
            const int AM[6] = {0, 1, 2, 0, 0, 1};
            const int BMx[6] = {0, 0, 0, 1, 2, 1};
            #pragma unroll
            for (int c6 = 0; c6 < 6; c6++)
                #pragma unroll
                for (int mf = 0; mf < 2; mf++)
                    #pragma unroll
                    for (int nf = 0; nf < 2; nf++)
                        mma16816(acc[c6][mf][nf], af[AM[c6]][mf], bfr[BMx[c6]][nf]);
        }
    }

    // ---- epilogue: score + packed (score,index) min-reduction --------------
    unsigned long long rk[2][2] = {{~0ull, ~0ull}, {~0ull, ~0ull}};  // [mf][rr]
    unsigned long long ck[2][2] = {{~0ull, ~0ull}, {~0ull, ~0ull}};  // [nf][c]

    #pragma unroll
    for (int mf = 0; mf < 2; mf++)
        #pragma unroll
        for (int rr = 0; rr < 2; rr++)
            #pragma unroll
            for (int nf = 0; nf < 2; nf++)
                #pragma unroll
                for (int c = 0; c < 2; c++) {
                    int idx = rr * 2 + c;
                    int il = wm * 32 + mf * 16 + rr * 8 + g;
                    int jl = wn * 16 + nf * 8 + tg * 2 + c;
                    int i = ib + il, j = jb + jl;
                    float nn = acc[0][mf][nf][idx];
                    if (i != j && nn > 1.5f && g_am[i] != g_am[j]) {
                        float ns = fmaxf(nn, 2.f);
                        float s1 = acc[1][mf][nf][idx] - acc[3][mf][nf][idx];
                        float s2 = acc[2][mf][nf][idx] - 2.f * acc[5][mf][nf][idx] + acc[4][mf][nf][idx];
                        float var = (s2 - s1 * s1 / ns) / (ns - 1.f);
                        rk[mf][rr] = ullmin2(rk[mf][rr], pack_key(var, j));
                        ck[nf][c]  = ullmin2(ck[nf][c],  pack_key(var, i));
                    }
                }

    // row-side: reduce over the 4 lanes of each quad (same row, different cols)
    #pragma unroll
    for (int mf = 0; mf < 2; mf++)
        #pragma unroll
        for (int rr = 0; rr < 2; rr++) {
            unsigned long long v = rk[mf][rr];
            v = ullmin2(v, __shfl_xor_sync(0xffffffffu, v, 1));
            v = ullmin2(v, __shfl_xor_sync(0xffffffffu, v, 2));
            if (tg == 0 && v != ~0ull)
                atomicMin(&keyI[wm * 32 + mf * 16 + rr * 8 + g], v);
        }
    // col-side: reduce over lanes sharing tg (same cols, different rows)
    #pragma unroll
    for (int nf = 0; nf < 2; nf++)
        #pragma unroll
        for (int c = 0; c < 2; c++) {
            unsigned long long v = ck[nf][c];
            v = ullmin2(v, __shfl_xor_sync(0xffffffffu, v, 4));
            v = ullmin2(v, __shfl_xor_sync(0xffffffffu, v, 8));
            v = ullmin2(v, __shfl_xor_sync(0xffffffffu, v, 16));
            if (g == 0 && v != ~0ull)
                atomicMin(&keyJ[wn * 16 + nf * 8 + tg * 2 + c], v);
        }

    __syncthreads();
    if (tid < 64) {
        if (keyI[tid] != ~0ull) atomicMin(&g_rowmin[ib + tid], keyI[tid]);
    } else if (tid < 128) {
        if (keyJ[tid - 64] != ~0ull) atomicMin(&g_rowmin[jb + tid - 64], keyJ[tid - 64]);
    }
}

// ---------------- kernel 3: row loss ||H[i] - H[argmin]|| -------------------
__global__ void rowloss_kernel(const float* __restrict__ H) {
    int i = blockIdx.x;
    int t = threadIdx.x;
    int j = (int)(g_rowmin[i] & 0xFFFFFFFFull);
    const size_t bi = (size_t)i * D_DIM, bj = (size_t)j * D_DIM;
    float s = 0.f;
    for (int d = t; d < D_DIM; d += 256) {
        float dv = H[bi + d] - H[bj + d];
        s += dv * dv;
    }
    __shared__ float sh[256];
    sh[t] = s; __syncthreads();
    for (int o = 128; o > 0; o >>= 1) { if (t < o) sh[t] += sh[t + o]; __syncthreads(); }
    if (t == 0) atomicAdd(&g_rowloss, sqrt((double)sh[0]));
}

// ---------------- kernel 4: combine -----------------------------------------
__global__ void final_kernel(float* out) {
    out[0] = (float)(g_mse + 10.0 * g_rowloss);
}

// ---------------- launch ------------------------------------------------------
extern "C" void kernel_launch(void* const* d_in, const int* in_sizes, int n_in,
                              void* d_out, int out_size) {
    const float* X = (const float*)d_in[0];
    const float* H = (const float*)d_in[1];
    const float* C = (const float*)d_in[2];
    const float* M = (const float*)d_in[3];
    (void)in_sizes; (void)n_in; (void)out_size;

    init_kernel<<<(T_DIM + 255) / 256, 256>>>();
    prep_kernel<<<T_DIM, 256>>>(X, H, C, M);
    dim3 grid(NBLK, NBLK);
    gemm_kernel<<<grid, 256>>>();
    rowloss_kernel<<<T_DIM, 256>>>(H);
    final_kernel<<<1, 1>>>((float*)d_out);
}

// round 2
// speedup vs baseline: 1.3921x; 1.3921x over previous
#include <cuda_runtime.h>
#include <cuda_bf16.h>
#include <math.h>

// Problem constants (fixed shapes per reference)
#define T_DIM 4096
#define D_DIM 1024
#define BM    128
#define BN    64
#define BK    32
#define NSTAGE 3
#define SSTR  40                                    // padded k-stride (bf16 elems)
#define A_ST_ELEMS (3 * BM * SSTR)                  // 15360
#define B_ST_ELEMS (3 * BN * SSTR)                  // 7680
#define ST_ELEMS   (A_ST_ELEMS + B_ST_ELEMS)        // 23040
#define SMEM_BYTES (NSTAGE * ST_ELEMS * 2)          // 138240

// ---------------- scratch (static device allocations; no cudaMalloc) -------
__device__ __nv_bfloat16 g_Mb [T_DIM * D_DIM];
__device__ __nv_bfloat16 g_MH [T_DIM * D_DIM];
__device__ __nv_bfloat16 g_MH2[T_DIM * D_DIM];
__device__ int                g_am[T_DIM];
__device__ unsigned long long g_rowmin[T_DIM];
__device__ double             g_mse;
__device__ double             g_rowloss;

// ---------------- helpers ---------------------------------------------------
__device__ __forceinline__ unsigned long long pack_key(float s, int idx) {
    unsigned int u = __float_as_uint(s);
    u = (u & 0x80000000u) ? ~u : (u | 0x80000000u);   // order-preserving float->uint
    return ((unsigned long long)u << 32) | (unsigned int)idx;
}
__device__ __forceinline__ unsigned long long ullmin2(unsigned long long a, unsigned long long b) {
    return a < b ? a : b;
}
__device__ __forceinline__ void mma16816(float* c, const unsigned* a, const unsigned* b) {
    asm volatile(
        "mma.sync.aligned.m16n8k16.row.col.f32.bf16.bf16.f32 "
        "{%0,%1,%2,%3}, {%4,%5,%6,%7}, {%8,%9}, {%0,%1,%2,%3};"
        : "+f"(c[0]), "+f"(c[1]), "+f"(c[2]), "+f"(c[3])
        : "r"(a[0]), "r"(a[1]), "r"(a[2]), "r"(a[3]), "r"(b[0]), "r"(b[1]));
}
__device__ __forceinline__ void ldsm_x4(unsigned* r, unsigned addr) {
    asm volatile("ldmatrix.sync.aligned.m8n8.x4.shared.b16 {%0,%1,%2,%3}, [%4];"
        : "=r"(r[0]), "=r"(r[1]), "=r"(r[2]), "=r"(r[3]) : "r"(addr));
}
__device__ __forceinline__ void cp_async16(unsigned saddr, const void* gaddr) {
    asm volatile("cp.async.cg.shared.global [%0], [%1], 16;" :: "r"(saddr), "l"(gaddr));
}
__device__ __forceinline__ void cp_commit() {
    asm volatile("cp.async.commit_group;");
}
__device__ __forceinline__ void cp_wait2() {
    asm volatile("cp.async.wait_group 2;");
}

// ---------------- kernel 0: reset accumulators / row-min keys ---------------
__global__ void init_kernel() {
    int t = blockIdx.x * blockDim.x + threadIdx.x;
    if (t < T_DIM) g_rowmin[t] = pack_key(9999.0f, 0);   // sentinel, index 0
    if (t == 0) { g_mse = 0.0; g_rowloss = 0.0; }
}

// ---------------- kernel 1: build bf16 operands, am[], masked MSE -----------
__global__ void prep_kernel(const float* __restrict__ X, const float* __restrict__ H,
                            const float* __restrict__ C, const float* __restrict__ M) {
    int i = blockIdx.x;
    int t = threadIdx.x;                       // 256 threads, 4 elems each
    const size_t base = (size_t)i * D_DIM;
    float4 m4 = *(const float4*)(M + base + t * 4);
    float4 h4 = *(const float4*)(H + base + t * 4);
    float4 x4 = *(const float4*)(X + base + t * 4);
    float4 c4 = *(const float4*)(C + base + t * 4);

    float mv[4] = {m4.x, m4.y, m4.z, m4.w};
    float hv[4] = {h4.x, h4.y, h4.z, h4.w};
    float xv[4] = {x4.x, x4.y, x4.z, x4.w};
    float cv[4] = {c4.x, c4.y, c4.z, c4.w};

    __nv_bfloat16 ob[4], oh[4], oh2[4];
    float bestv = 3.4e38f; int besti = 0;
    float msum = 0.f;
    #pragma unroll
    for (int q = 0; q < 4; q++) {
        float mb = (mv[q] > 0.f) ? 1.f : 0.f;
        ob[q]  = __float2bfloat16(mb);
        oh[q]  = __float2bfloat16(mb * hv[q]);
        oh2[q] = __float2bfloat16(mb * hv[q] * hv[q]);
        float e = (xv[q] - (hv[q] - cv[q])) * mv[q];
        msum += e * e;
        if (mv[q] < bestv) { bestv = mv[q]; besti = t * 4 + q; }
    }
    *(uint2*)(g_Mb  + base + t * 4) = *(uint2*)ob;
    *(uint2*)(g_MH  + base + t * 4) = *(uint2*)oh;
    *(uint2*)(g_MH2 + base + t * 4) = *(uint2*)oh2;

    __shared__ float sv[256]; __shared__ int si[256]; __shared__ float ss[256];
    sv[t] = bestv; si[t] = besti; ss[t] = msum;
    __syncthreads();
    for (int o = 128; o > 0; o >>= 1) {
        if (t < o) {
            if (sv[t + o] < sv[t] || (sv[t + o] == sv[t] && si[t + o] < si[t])) {
                sv[t] = sv[t + o]; si[t] = si[t + o];
            }
            ss[t] += ss[t + o];
        }
        __syncthreads();
    }
    if (t == 0) {
        g_am[i] = si[0];
        atomicAdd(&g_mse, (double)ss[0]);
    }
}

// ---------------- kernel 2: fused 3-accumulator GEMM + score argmin ---------
// acc_n  = Mb_i.Mb_j            (exact)
// acc_s1 = Mb_i.MH_j - MH_i.Mb_j         (= -s1, used squared)
// acc_s2 = MH2_i.Mb_j - 2 MH_i.MH_j + Mb_i.MH2_j
extern __shared__ __align__(16) __nv_bfloat16 dynsmem[];

__global__ __launch_bounds__(256, 1)
void gemm_kernel() {
    const int bi = blockIdx.y, bj = blockIdx.x;
    if (bj < 2 * bi) return;                    // triangular cover: j-block >= start of i-block

    __shared__ unsigned long long keyI[BM], keyJ[BN];

    const int tid  = threadIdx.x;
    const int lane = tid & 31;
    const int warp = tid >> 5;
    const int wm = warp >> 1;                  // 0..3 -> 32-row slab
    const int wn = warp & 1;                   // 0..1 -> 32-col slab
    const int g  = lane >> 2;
    const int tg = lane & 3;

    if (tid < BM)                 keyI[tid]       = ~0ull;
    else if (tid < BM + BN)       keyJ[tid - BM]  = ~0ull;

    const int ib = bi * BM, jb = bj * BN;
    const unsigned smem_u32 = (unsigned)__cvta_generic_to_shared(dynsmem);
    const __nv_bfloat16* const gms[3] = {g_Mb, g_MH, g_MH2};

    float acc[3][2][4][4];
    #pragma unroll
    for (int p = 0; p < 3; p++)
        #pragma unroll
        for (int a = 0; a < 2; a++)
            #pragma unroll
            for (int b = 0; b < 4; b++)
                #pragma unroll
                for (int c = 0; c < 4; c++) acc[p][a][b][c] = 0.f;

    // ---- async stage loader --------------------------------------------
    auto load_stage = [&](int stage, int k0) {
        unsigned sbase = smem_u32 + stage * ST_ELEMS * 2;
        #pragma unroll
        for (int it = 0; it < 6; it++) {            // A: 3 ops x 128 rows x 4 chunks
            int c = tid + it * 256;
            int op = c >> 9, rem = c & 511, row = rem >> 2, kc = rem & 3;
            const __nv_bfloat16* gp = gms[op] + (size_t)(ib + row) * D_DIM + k0 + kc * 8;
            cp_async16(sbase + (op * BM * SSTR + row * SSTR + kc * 8) * 2, gp);
        }
        #pragma unroll
        for (int it = 0; it < 3; it++) {            // B: 3 ops x 64 rows x 4 chunks
            int c = tid + it * 256;
            int op = c >> 8, rem = c & 255, row = rem >> 2, kc = rem & 3;
            const __nv_bfloat16* gp = gms[op] + (size_t)(jb + row) * D_DIM + k0 + kc * 8;
            cp_async16(sbase + (A_ST_ELEMS + op * BN * SSTR + row * SSTR + kc * 8) * 2, gp);
        }
    };

    // ldmatrix per-lane address offsets (in elements, within a 16x16 chunk)
    const int a_lrow = lane & 15;                  // rows r0 + 0..15
    const int a_lcol = (lane >> 4) * 8;            // k  + 0 / +8
    const int b_lrow = (lane & 7) + (lane >> 4) * 8;  // cols n0 + 0..7 / +8..15
    const int b_lcol = ((lane >> 3) & 1) * 8;         // k + 0 / +8

    load_stage(0, 0); cp_commit();
    load_stage(1, BK); cp_commit();

    const int NT = D_DIM / BK;                     // 32
    for (int kt = 0; kt < NT; kt++) {
        if (kt + 2 < NT) load_stage((kt + 2) % NSTAGE, (kt + 2) * BK);
        cp_commit();
        cp_wait2();
        __syncthreads();

        unsigned sbase = smem_u32 + (kt % NSTAGE) * ST_ELEMS * 2;
        #pragma unroll
        for (int kk = 0; kk < BK; kk += 16) {
            unsigned af[3][2][4];
            unsigned bfr[3][4][2];
            #pragma unroll
            for (int m = 0; m < 3; m++) {
                #pragma unroll
                for (int mf = 0; mf < 2; mf++) {
                    int r0 = wm * 32 + mf * 16;
                    unsigned addr = sbase + (m * BM * SSTR + (r0 + a_lrow) * SSTR + kk + a_lcol) * 2;
                    ldsm_x4(af[m][mf], addr);
                }
                #pragma unroll
                for (int ng = 0; ng < 2; ng++) {
                    int n0 = wn * 32 + ng * 16;
                    unsigned addr = sbase + (A_ST_ELEMS + m * BN * SSTR + (n0 + b_lrow) * SSTR + kk + b_lcol) * 2;
                    unsigned r[4];
                    ldsm_x4(r, addr);
                    bfr[m][2 * ng    ][0] = r[0]; bfr[m][2 * ng    ][1] = r[1];
                    bfr[m][2 * ng + 1][0] = r[2]; bfr[m][2 * ng + 1][1] = r[3];
                }
            }
            // derived B fragments: -Mb (exact sign flip), -2*MH (exact pow2 scale)
            unsigned nMb[4][2], m2MH[4][2];
            const __nv_bfloat162 neg2 = __floats2bfloat162_rn(-2.f, -2.f);
            #pragma unroll
            for (int nf = 0; nf < 4; nf++)
                #pragma unroll
                for (int r = 0; r < 2; r++) {
                    nMb[nf][r] = bfr[0][nf][r] ^ 0x80008000u;
                    __nv_bfloat162 v = *reinterpret_cast<__nv_bfloat162*>(&bfr[1][nf][r]);
                    v = __hmul2(v, neg2);
                    m2MH[nf][r] = *reinterpret_cast<unsigned*>(&v);
                }
            #pragma unroll
            for (int mf = 0; mf < 2; mf++)
                #pragma unroll
                for (int nf = 0; nf < 4; nf++) {
                    mma16816(acc[0][mf][nf], af[0][mf], bfr[0][nf]);  // n
                    mma16816(acc[1][mf][nf], af[0][mf], bfr[1][nf]);  // +Mb.MH
                    mma16816(acc[1][mf][nf], af[1][mf], nMb[nf]);     // -MH.Mb
                    mma16816(acc[2][mf][nf], af[2][mf], bfr[0][nf]);  // MH2.Mb
                    mma16816(acc[2][mf][nf], af[1][mf], m2MH[nf]);    // -2 MH.MH
                    mma16816(acc[2][mf][nf], af[0][mf], bfr[2][nf]);  // Mb.MH2
                }
        }
        __syncthreads();
    }

    // ---- epilogue: score + packed (score,index) min-reduction --------------
    unsigned long long rk[2][2] = {{~0ull, ~0ull}, {~0ull, ~0ull}};  // [mf][rr]
    unsigned long long ck[4][2] = {{~0ull,~0ull},{~0ull,~0ull},{~0ull,~0ull},{~0ull,~0ull}}; // [nf][c]

    #pragma unroll
    for (int mf = 0; mf < 2; mf++)
        #pragma unroll
        for (int rr = 0; rr < 2; rr++)
            #pragma unroll
            for (int nf = 0; nf < 4; nf++)
                #pragma unroll
                for (int c = 0; c < 2; c++) {
                    int idx = rr * 2 + c;
                    int il = wm * 32 + mf * 16 + rr * 8 + g;
                    int jl = wn * 32 + nf * 8 + tg * 2 + c;
                    int i = ib + il, j = jb + jl;
                    float nn = acc[0][mf][nf][idx];
                    if (i != j && nn > 1.5f && g_am[i] != g_am[j]) {
                        float ns = fmaxf(nn, 2.f);
                        float s1 = acc[1][mf][nf][idx];
                        float s2 = acc[2][mf][nf][idx];
                        float var = (s2 - s1 * s1 / ns) / (ns - 1.f);
                        rk[mf][rr] = ullmin2(rk[mf][rr], pack_key(var, j));
                        ck[nf][c]  = ullmin2(ck[nf][c],  pack_key(var, i));
                    }
                }

    // row-side: reduce over quad lanes (same row, different cols)
    #pragma unroll
    for (int mf = 0; mf < 2; mf++)
        #pragma unroll
        for (int rr = 0; rr < 2; rr++) {
            unsigned long long v = rk[mf][rr];
            v = ullmin2(v, __shfl_xor_sync(0xffffffffu, v, 1));
            v = ullmin2(v, __shfl_xor_sync(0xffffffffu, v, 2));
            if (tg == 0 && v != ~0ull)
                atomicMin(&keyI[wm * 32 + mf * 16 + rr * 8 + g], v);
        }
    // col-side: reduce over lanes sharing tg (same cols, different rows)
    #pragma unroll
    for (int nf = 0; nf < 4; nf++)
        #pragma unroll
        for (int c = 0; c < 2; c++) {
            unsigned long long v = ck[nf][c];
            v = ullmin2(v, __shfl_xor_sync(0xffffffffu, v, 4));
            v = ullmin2(v, __shfl_xor_sync(0xffffffffu, v, 8));
            v = ullmin2(v, __shfl_xor_sync(0xffffffffu, v, 16));
            if (g == 0 && v != ~0ull)
                atomicMin(&keyJ[wn * 32 + nf * 8 + tg * 2 + c], v);
        }

    __syncthreads();
    if (tid < BM) {
        if (keyI[tid] != ~0ull) atomicMin(&g_rowmin[ib + tid], keyI[tid]);
    } else if (tid < BM + BN) {
        if (keyJ[tid - BM] != ~0ull) atomicMin(&g_rowmin[jb + tid - BM], keyJ[tid - BM]);
    }
}

// ---------------- kernel 3: row loss ||H[i] - H[argmin]|| -------------------
__global__ void rowloss_kernel(const float* __restrict__ H) {
    int i = blockIdx.x;
    int t = threadIdx.x;                           // 256 threads x float4
    int j = (int)(g_rowmin[i] & 0xFFFFFFFFull);
    float4 va = *(const float4*)(H + (size_t)i * D_DIM + t * 4);
    float4 vb = *(const float4*)(H + (size_t)j * D_DIM + t * 4);
    float dx = va.x - vb.x, dy = va.y - vb.y, dz = va.z - vb.z, dw = va.w - vb.w;
    float s = dx * dx + dy * dy + dz * dz + dw * dw;
    __shared__ float sh[256];
    sh[t] = s; __syncthreads();
    for (int o = 128; o > 0; o >>= 1) { if (t < o) sh[t] += sh[t + o]; __syncthreads(); }
    if (t == 0) atomicAdd(&g_rowloss, sqrt((double)sh[0]));
}

// ---------------- kernel 4: combine -----------------------------------------
__global__ void final_kernel(float* out) {
    out[0] = (float)(g_mse + 10.0 * g_rowloss);
}

// ---------------- launch ------------------------------------------------------
extern "C" void kernel_launch(void* const* d_in, const int* in_sizes, int n_in,
                              void* d_out, int out_size) {
    const float* X = (const float*)d_in[0];
    const float* H = (const float*)d_in[1];
    const float* C = (const float*)d_in[2];
    const float* M = (const float*)d_in[3];
    (void)in_sizes; (void)n_in; (void)out_size;

    cudaFuncSetAttribute(gemm_kernel, cudaFuncAttributeMaxDynamicSharedMemorySize, SMEM_BYTES);

    init_kernel<<<(T_DIM + 255) / 256, 256>>>();
    prep_kernel<<<T_DIM, 256>>>(X, H, C, M);
    dim3 grid(T_DIM / BN, T_DIM / BM);             // (64, 32)
    gemm_kernel<<<grid, 256, SMEM_BYTES>>>();
    rowloss_kernel<<<T_DIM, 256>>>(H);
    final_kernel<<<1, 1>>>((float*)d_out);
}

// round 4
// speedup vs baseline: 1.9336x; 1.3890x over previous
#include <cuda_runtime.h>
#include <cuda_bf16.h>
#include <math.h>
#include <stdint.h>

// Problem constants (fixed shapes per reference)
#define T_DIM 4096
#define D_DIM 1024
#define BM    128
#define BN    64
#define BK    64
#define NT    (D_DIM / BK)          // 16 k-tiles

#define A_OP_BYTES (BM * 128)       // 128 rows x 128B (BK=64 bf16)
#define B_OP_BYTES (BN * 128)       // 64 rows x 128B
#define A_BYTES    (4 * A_OP_BYTES) // 65536
#define B_BYTES    (3 * B_OP_BYTES) // 24576
#define STAGE_BYTES (A_BYTES + B_BYTES)  // 90112
#define NSTAGE 2

#define AUX_OFF   (NSTAGE * STAGE_BYTES)    // 180224
#define KEYI_OFF  (AUX_OFF)                 // 128*8
#define KEYJ_OFF  (AUX_OFF + 1024)          // 64*8
#define AMJ_OFF   (AUX_OFF + 1536)          // 64*4
#define AUX_BYTES 1792
#define SMEM_REQ  (AUX_OFF + AUX_BYTES + 1008)

// ---------------- scratch (static device allocations; no cudaMalloc) -------
__device__ __nv_bfloat16 g_Mb  [T_DIM * D_DIM];
__device__ __nv_bfloat16 g_MH  [T_DIM * D_DIM];
__device__ __nv_bfloat16 g_MH2 [T_DIM * D_DIM];
__device__ __nv_bfloat16 g_nMH [T_DIM * D_DIM];   // -MH
__device__ __nv_bfloat16 g_n2MH[T_DIM * D_DIM];   // -2*MH
__device__ int                g_am[T_DIM];
__device__ unsigned long long g_rowmin[T_DIM];
__device__ double             g_mse;
__device__ double             g_rowloss;

// ---------------- helpers ---------------------------------------------------
__device__ __forceinline__ unsigned long long pack_key(float s, int idx) {
    unsigned int u = __float_as_uint(s);
    u = (u & 0x80000000u) ? ~u : (u | 0x80000000u);   // order-preserving float->uint
    return ((unsigned long long)u << 32) | (unsigned int)idx;
}
__device__ __forceinline__ unsigned long long ullmin2(unsigned long long a, unsigned long long b) {
    return a < b ? a : b;
}
__device__ __forceinline__ void mma16816(float* c, const unsigned* a, const unsigned* b) {
    asm volatile(
        "mma.sync.aligned.m16n8k16.row.col.f32.bf16.bf16.f32 "
        "{%0,%1,%2,%3}, {%4,%5,%6,%7}, {%8,%9}, {%0,%1,%2,%3};"
        : "+f"(c[0]), "+f"(c[1]), "+f"(c[2]), "+f"(c[3])
        : "r"(a[0]), "r"(a[1]), "r"(a[2]), "r"(a[3]), "r"(b[0]), "r"(b[1]));
}
__device__ __forceinline__ void ldsm_x4(unsigned* r, unsigned addr) {
    asm volatile("ldmatrix.sync.aligned.m8n8.x4.shared.b16 {%0,%1,%2,%3}, [%4];"
        : "=r"(r[0]), "=r"(r[1]), "=r"(r[2]), "=r"(r[3]) : "r"(addr));
}
__device__ __forceinline__ void cp_async16(unsigned saddr, const void* gaddr) {
    asm volatile("cp.async.cg.shared.global [%0], [%1], 16;" :: "r"(saddr), "l"(gaddr));
}
__device__ __forceinline__ void cp_commit() { asm volatile("cp.async.commit_group;"); }
__device__ __forceinline__ void cp_wait1()  { asm volatile("cp.async.wait_group 1;"); }
__device__ __forceinline__ void cp_wait0()  { asm volatile("cp.async.wait_group 0;"); }

// ---------------- kernel 0: reset accumulators / row-min keys ---------------
__global__ void init_kernel() {
    int t = blockIdx.x * blockDim.x + threadIdx.x;
    if (t < T_DIM) g_rowmin[t] = pack_key(9999.0f, 0);
    if (t == 0) { g_mse = 0.0; g_rowloss = 0.0; }
}

// ---------------- kernel 1: build bf16 operands, am[], masked MSE -----------
__global__ void prep_kernel(const float* __restrict__ X, const float* __restrict__ H,
                            const float* __restrict__ C, const float* __restrict__ M) {
    int i = blockIdx.x;
    int t = threadIdx.x;                       // 256 threads, 4 elems each
    const size_t base = (size_t)i * D_DIM;
    float4 m4 = *(const float4*)(M + base + t * 4);
    float4 h4 = *(const float4*)(H + base + t * 4);
    float4 x4 = *(const float4*)(X + base + t * 4);
    float4 c4 = *(const float4*)(C + base + t * 4);

    float mv[4] = {m4.x, m4.y, m4.z, m4.w};
    float hv[4] = {h4.x, h4.y, h4.z, h4.w};
    float xv[4] = {x4.x, x4.y, x4.z, x4.w};
    float cv[4] = {c4.x, c4.y, c4.z, c4.w};

    __nv_bfloat16 ob[4], oh[4], oh2[4], onh[4], on2h[4];
    float bestv = 3.4e38f; int besti = 0;
    float msum = 0.f;
    #pragma unroll
    for (int q = 0; q < 4; q++) {
        float mb = (mv[q] > 0.f) ? 1.f : 0.f;
        ob[q]  = __float2bfloat16(mb);
        oh[q]  = __float2bfloat16(mb * hv[q]);
        oh2[q] = __float2bfloat16(mb * hv[q] * hv[q]);
        float ohf = __bfloat162float(oh[q]);            // bf16-rounded MH
        onh[q]  = __float2bfloat16(-ohf);               // exact negation
        on2h[q] = __float2bfloat16(-2.f * ohf);         // exact pow2 scale
        float e = (xv[q] - (hv[q] - cv[q])) * mv[q];
        msum += e * e;
        if (mv[q] < bestv) { bestv = mv[q]; besti = t * 4 + q; }
    }
    *(uint2*)(g_Mb   + base + t * 4) = *(uint2*)ob;
    *(uint2*)(g_MH   + base + t * 4) = *(uint2*)oh;
    *(uint2*)(g_MH2  + base + t * 4) = *(uint2*)oh2;
    *(uint2*)(g_nMH  + base + t * 4) = *(uint2*)onh;
    *(uint2*)(g_n2MH + base + t * 4) = *(uint2*)on2h;

    __shared__ float sv[256]; __shared__ int si[256]; __shared__ float ss[256];
    sv[t] = bestv; si[t] = besti; ss[t] = msum;
    __syncthreads();
    for (int o = 128; o > 0; o >>= 1) {
        if (t < o) {
            if (sv[t + o] < sv[t] || (sv[t + o] == sv[t] && si[t + o] < si[t])) {
                sv[t] = sv[t + o]; si[t] = si[t + o];
            }
            ss[t] += ss[t + o];
        }
        __syncthreads();
    }
    if (t == 0) {
        g_am[i] = si[0];
        atomicAdd(&g_mse, (double)ss[0]);
    }
}

// ---------------- kernel 2: fused 3-accumulator GEMM + score argmin ---------
// acc0 = Mb_i.Mb_j   acc1 = Mb_i.MH_j + (-MH)_i.Mb_j   (= -s1, squared)
// acc2 = MH2_i.Mb_j + (-2MH)_i.MH_j + Mb_i.MH2_j
extern __shared__ char dynsmem[];

__global__ __launch_bounds__(512, 1)
void gemm_kernel() {
    const int bi = blockIdx.y, bj = blockIdx.x;
    if (bj < 2 * bi) return;                    // triangular cover

    const int tid  = threadIdx.x;
    const int lane = tid & 31;
    const int warp = tid >> 5;
    const int wm = warp >> 1;                   // 0..7 -> 16-row slab
    const int wn = warp & 1;                    // 0..1 -> 32-col slab
    const int g  = lane >> 2;
    const int tg = lane & 3;
    const int ib = bi * BM, jb = bj * BN;

    unsigned raw = (unsigned)__cvta_generic_to_shared(dynsmem);
    unsigned sb0 = (raw + 1023u) & ~1023u;      // 1024-aligned stage area
    char* auxg = dynsmem + (sb0 - raw);
    unsigned long long* keyI = (unsigned long long*)(auxg + KEYI_OFF);
    unsigned long long* keyJ = (unsigned long long*)(auxg + KEYJ_OFF);
    int* s_amJ = (int*)(auxg + AMJ_OFF);

    if (tid < BM)                 keyI[tid]      = ~0ull;
    else if (tid < BM + BN) {     keyJ[tid - BM] = ~0ull; s_amJ[tid - BM] = g_am[jb + tid - BM]; }

    float acc[3][4][4];
    #pragma unroll
    for (int p = 0; p < 3; p++)
        #pragma unroll
        for (int b = 0; b < 4; b++)
            #pragma unroll
            for (int c = 0; c < 4; c++) acc[p][b][c] = 0.f;

    const __nv_bfloat16* const matsA[4] = {g_Mb, g_nMH, g_n2MH, g_MH2};
    const __nv_bfloat16* const matsB[3] = {g_Mb, g_MH, g_MH2};

    // ---- stage loader: swizzled 16B chunks ----------------------------------
    auto load_stage = [&](int stage, int kt) {
        unsigned sb = sb0 + stage * STAGE_BYTES;
        int kcol = kt * BK;
        #pragma unroll
        for (int it = 0; it < 8; it++) {           // A: 4 ops x 128 rows x 8 chunks
            int id = tid + it * 512;
            int op = id >> 10, rem = id & 1023, r = rem >> 3, c = rem & 7;
            const __nv_bfloat16* gp = matsA[op] + (size_t)(ib + r) * D_DIM + kcol + c * 8;
            cp_async16(sb + op * A_OP_BYTES + r * 128 + (((unsigned)(c ^ (r & 7))) << 4), gp);
        }
        #pragma unroll
        for (int it = 0; it < 3; it++) {           // B: 3 ops x 64 rows x 8 chunks
            int id = tid + it * 512;
            int op = id >> 9, rem = id & 511, r = rem >> 3, c = rem & 7;
            const __nv_bfloat16* gp = matsB[op] + (size_t)(jb + r) * D_DIM + kcol + c * 8;
            cp_async16(sb + A_BYTES + op * B_OP_BYTES + r * 128 + (((unsigned)(c ^ (r & 7))) << 4), gp);
        }
    };

    // ldmatrix per-lane geometry
    const int a_row  = wm * 16 + (lane & 15);       // A row this lane addresses
    const int a_half = lane >> 4;                   // chunk offset 0/1
    const int b_lrow = (lane & 7) + ((lane >> 4) << 3);
    const int b_half = (lane >> 3) & 1;

    load_stage(0, 0);
    cp_commit();

    #pragma unroll 1
    for (int kt = 0; kt < NT; kt++) {
        if (kt + 1 < NT) { load_stage((kt + 1) & 1, kt + 1); cp_commit(); cp_wait1(); }
        else             { cp_wait0(); }
        __syncthreads();

        unsigned sb = sb0 + (kt & 1) * STAGE_BYTES;
        #pragma unroll
        for (int kk8 = 0; kk8 < 8; kk8 += 2) {       // 4 k-chunks of 16
            // B fragments: 3 ops x 4 nf x 2 regs
            unsigned bf[3][4][2];
            #pragma unroll
            for (int m = 0; m < 3; m++)
                #pragma unroll
                for (int ng = 0; ng < 2; ng++) {
                    int row = wn * 32 + ng * 16 + b_lrow;
                    unsigned addr = sb + A_BYTES + m * B_OP_BYTES + row * 128
                                  + (((unsigned)((kk8 + b_half) ^ (row & 7))) << 4);
                    unsigned r[4]; ldsm_x4(r, addr);
                    bf[m][2 * ng][0] = r[0]; bf[m][2 * ng][1] = r[1];
                    bf[m][2 * ng + 1][0] = r[2]; bf[m][2 * ng + 1][1] = r[3];
                }
            unsigned achunk = ((unsigned)((kk8 + a_half) ^ (a_row & 7))) << 4;
            unsigned arow_off = a_row * 128 + achunk;
            {   // A0 = Mb: acc0 += A0*B0, acc1 += A0*B1, acc2 += A0*B2
                unsigned a[4]; ldsm_x4(a, sb + 0 * A_OP_BYTES + arow_off);
                #pragma unroll
                for (int nf = 0; nf < 4; nf++) {
                    mma16816(acc[0][nf], a, bf[0][nf]);
                    mma16816(acc[1][nf], a, bf[1][nf]);
                    mma16816(acc[2][nf], a, bf[2][nf]);
                }
            }
            {   // A1 = -MH: acc1 += A1*B0
                unsigned a[4]; ldsm_x4(a, sb + 1 * A_OP_BYTES + arow_off);
                #pragma unroll
                for (int nf = 0; nf < 4; nf++) mma16816(acc[1][nf], a, bf[0][nf]);
            }
            {   // A2 = -2MH: acc2 += A2*B1
                unsigned a[4]; ldsm_x4(a, sb + 2 * A_OP_BYTES + arow_off);
                #pragma unroll
                for (int nf = 0; nf < 4; nf++) mma16816(acc[2][nf], a, bf[1][nf]);
            }
            {   // A3 = MH2: acc2 += A3*B0
                unsigned a[4]; ldsm_x4(a, sb + 3 * A_OP_BYTES + arow_off);
                #pragma unroll
                for (int nf = 0; nf < 4; nf++) mma16816(acc[2][nf], a, bf[0][nf]);
            }
        }
        __syncthreads();                          // protect stage before overwrite
    }

    // ---- epilogue: score + packed (score,index) min-reduction --------------
    const int i0 = ib + wm * 16 + g;              // rr=0 row
    const int am0 = g_am[i0];
    const int am1 = g_am[i0 + 8];
    unsigned long long rk[2] = {~0ull, ~0ull};
    unsigned long long ck[4][2] = {{~0ull,~0ull},{~0ull,~0ull},{~0ull,~0ull},{~0ull,~0ull}};

    #pragma unroll
    for (int nf = 0; nf < 4; nf++)
        #pragma unroll
        for (int idx = 0; idx < 4; idx++) {
            int rr = idx >> 1, c = idx & 1;
            int i = i0 + rr * 8;
            int jl = wn * 32 + nf * 8 + tg * 2 + c;
            int j = jb + jl;
            float nn = acc[0][nf][idx];
            int ami = rr ? am1 : am0;
            if (i != j && nn > 1.5f && ami != s_amJ[jl]) {
                float ns = fmaxf(nn, 2.f);
                float s1 = acc[1][nf][idx];
                float s2 = acc[2][nf][idx];
                float var = (s2 - s1 * s1 / ns) / (ns - 1.f);
                rk[rr] = ullmin2(rk[rr], pack_key(var, j));
                ck[nf][c] = ullmin2(ck[nf][c], pack_key(var, i));
            }
        }

    // row-side: min over quad lanes (same row, different cols)
    #pragma unroll
    for (int rr = 0; rr < 2; rr++) {
        unsigned long long v = rk[rr];
        v = ullmin2(v, __shfl_xor_sync(0xffffffffu, v, 1));
        v = ullmin2(v, __shfl_xor_sync(0xffffffffu, v, 2));
        if (tg == 0 && v != ~0ull)
            atomicMin(&keyI[wm * 16 + rr * 8 + g], v);
    }
    // col-side: min over lanes sharing tg (same cols, different rows)
    #pragma unroll
    for (int nf = 0; nf < 4; nf++)
        #pragma unroll
        for (int c = 0; c < 2; c++) {
            unsigned long long v = ck[nf][c];
            v = ullmin2(v, __shfl_down_sync(0xffffffffu, v, 4));
            v = ullmin2(v, __shfl_down_sync(0xffffffffu, v, 8));
            v = ullmin2(v, __shfl_down_sync(0xffffffffu, v, 16));
            if (g == 0 && v != ~0ull)
                atomicMin(&keyJ[wn * 32 + nf * 8 + tg * 2 + c], v);
        }

    __syncthreads();
    if (tid < BM) {
        if (keyI[tid] != ~0ull) atomicMin(&g_rowmin[ib + tid], keyI[tid]);
    } else if (tid < BM + BN) {
        if (keyJ[tid - BM] != ~0ull) atomicMin(&g_rowmin[jb + tid - BM], keyJ[tid - BM]);
    }
}

// ---------------- kernel 3: row loss ||H[i] - H[argmin]|| -------------------
__global__ void rowloss_kernel(const float* __restrict__ H) {
    int i = blockIdx.x;
    int t = threadIdx.x;                           // 256 threads x float4
    int j = (int)(g_rowmin[i] & 0xFFFFFFFFull);
    float4 va = *(const float4*)(H + (size_t)i * D_DIM + t * 4);
    float4 vb = *(const float4*)(H + (size_t)j * D_DIM + t * 4);
    float dx = va.x - vb.x, dy = va.y - vb.y, dz = va.z - vb.z, dw = va.w - vb.w;
    float s = dx * dx + dy * dy + dz * dz + dw * dw;
    __shared__ float sh[256];
    sh[t] = s; __syncthreads();
    for (int o = 128; o > 0; o >>= 1) { if (t < o) sh[t] += sh[t + o]; __syncthreads(); }
    if (t == 0) atomicAdd(&g_rowloss, sqrt((double)sh[0]));
}

// ---------------- kernel 4: combine -----------------------------------------
__global__ void final_kernel(float* out) {
    out[0] = (float)(g_mse + 10.0 * g_rowloss);
}

// ---------------- launch ------------------------------------------------------
extern "C" void kernel_launch(void* const* d_in, const int* in_sizes, int n_in,
                              void* d_out, int out_size) {
    const float* X = (const float*)d_in[0];
    const float* H = (const float*)d_in[1];
    const float* C = (const float*)d_in[2];
    const float* M = (const float*)d_in[3];
    (void)in_sizes; (void)n_in; (void)out_size;

    cudaFuncSetAttribute(gemm_kernel, cudaFuncAttributeMaxDynamicSharedMemorySize, SMEM_REQ);

    init_kernel<<<(T_DIM + 255) / 256, 256>>>();
    prep_kernel<<<T_DIM, 256>>>(X, H, C, M);
    dim3 grid(T_DIM / BN, T_DIM / BM);             // (64, 32), bj < 2*bi exits early
    gemm_kernel<<<grid, 512, SMEM_REQ>>>();
    rowloss_kernel<<<T_DIM, 256>>>(H);
    final_kernel<<<1, 1>>>((float*)d_out);
}